// round 7
// baseline (speedup 1.0000x reference)
#include <cuda_runtime.h>
#include <stdint.h>

// Fixed problem shapes
#define BQ 2
#define NQ 16384
#define SQ 4096
#define CQ 64
#define NS 32
#define OUTC 67
#define NCELL 1000            // 10x10x10 grid, cell = radius = 0.1
#define WARPS_B 8             // centers per ball-query block
#define HB 64                 // wide hist/scatter blocks
#define NTILE 2048            // transpose tiles (512 n x 2 c x 2 b)

// Device scratch (no allocations allowed). g_cellcnt starts zero (static
// init) and is re-zeroed by k2 each replay -> pipeline stateless under graphs.
__device__ float4 g_xyzp[BQ * NQ];                  // packed xyz, cell id in .w
__device__ float4 g_sorted[BQ * NQ];                // cell-sorted xyz, orig idx in .w
__device__ float  g_featT[(size_t)BQ * NQ * CQ];    // features [B,N,C]
__device__ int    g_idx[BQ * SQ * NS];              // final sample indices
__device__ int    g_cellcnt[BQ * NCELL];            // histogram
__device__ int    g_cellstart[BQ * (NCELL + 1)];    // exclusive prefix, [1000] = N
__device__ int    g_cellfill[BQ * NCELL];           // scatter cursors

__device__ __forceinline__ int cell_of(float v) {
    int c = (int)(v * 10.0f);
    return min(9, max(0, c));
}

// one 32x32 transpose tile of [B,C,N] -> [B,N,C]; id in [0, NTILE)
__device__ __forceinline__ void transpose_tile(const float* __restrict__ feat, int id) {
    __shared__ float tile[32][33];
    int n0 = (id & 511) * 32;
    int c0 = ((id >> 9) & 1) * 32;
    int b  = id >> 10;
    int tx = threadIdx.x & 31;
    int ty = threadIdx.x >> 5;                      // 0..7

#pragma unroll
    for (int j = 0; j < 32; j += 8)
        tile[ty + j][tx] = feat[((size_t)b * CQ + (c0 + ty + j)) * NQ + (n0 + tx)];
    __syncthreads();
#pragma unroll
    for (int j = 0; j < 32; j += 8)
        g_featT[((size_t)b * NQ + (n0 + ty + j)) * CQ + (c0 + tx)] = tile[tx][ty + j];
}

// ---------------------------------------------------------------------------
// K1: blocks 0..HB-1 = pack + global-atomic histogram; rest = ALL transpose
// ---------------------------------------------------------------------------
__global__ __launch_bounds__(256)
void k1_hist(const float* __restrict__ xyz, const float* __restrict__ feat) {
    if (blockIdx.x < HB) {
        int i = blockIdx.x * (BQ * NQ / HB) + threadIdx.x;   // 512 pts per block
        int end = (blockIdx.x + 1) * (BQ * NQ / HB);
        for (; i < end; i += 256) {
            float x = xyz[3 * i + 0], y = xyz[3 * i + 1], z = xyz[3 * i + 2];
            int cell = (cell_of(z) * 10 + cell_of(y)) * 10 + cell_of(x);
            g_xyzp[i] = make_float4(x, y, z, __int_as_float(cell));
            int b = i >> 14;
            atomicAdd(&g_cellcnt[b * NCELL + cell], 1);
        }
    } else {
        transpose_tile(feat, blockIdx.x - HB);               // all 2048 tiles
    }
}

// ---------------------------------------------------------------------------
// K2: per-batch scan over 1000 cells (hierarchical, 3 barriers);
//     re-zeroes counts, fills cellstart + cursors.
// ---------------------------------------------------------------------------
__global__ __launch_bounds__(256)
void k2_scan() {
    __shared__ int wsum[8];
    __shared__ int wbase[8];
    const int b = blockIdx.x;
    const int t = threadIdx.x;
    const int lane = t & 31, wid = t >> 5;

    int cnt4[4];
    int own = 0;
    if (t < 250) {
#pragma unroll
        for (int j = 0; j < 4; j++) {
            cnt4[j] = g_cellcnt[b * NCELL + 4 * t + j];
            own += cnt4[j];
        }
    }
    // warp inclusive scan of own
    int inc = own;
#pragma unroll
    for (int d = 1; d < 32; d <<= 1) {
        int v = __shfl_up_sync(0xffffffffu, inc, d);
        if (lane >= d) inc += v;
    }
    if (lane == 31) wsum[wid] = inc;
    __syncthreads();
    if (t == 0) {
        int run = 0;
#pragma unroll
        for (int w = 0; w < 8; w++) { wbase[w] = run; run += wsum[w]; }
    }
    __syncthreads();

    if (t < 250) {
        int run = wbase[wid] + inc - own;            // exclusive base
#pragma unroll
        for (int j = 0; j < 4; j++) {
            int bin = 4 * t + j;
            g_cellstart[b * (NCELL + 1) + bin] = run;
            g_cellfill[b * NCELL + bin] = run;
            g_cellcnt[b * NCELL + bin] = 0;          // stateless for replay
            run += cnt4[j];
        }
    }
    if (t == 0) g_cellstart[b * (NCELL + 1) + NCELL] = NQ;
}

// ---------------------------------------------------------------------------
// K3: scatter into cell order (cell id cached in g_xyzp.w)
// ---------------------------------------------------------------------------
__global__ __launch_bounds__(256)
void k3_scatter() {
    int i = blockIdx.x * (BQ * NQ / HB) + threadIdx.x;
    int end = (blockIdx.x + 1) * (BQ * NQ / HB);
    for (; i < end; i += 256) {
        float4 p = g_xyzp[i];
        int cell = __float_as_int(p.w);
        int b = i >> 14, n = i & (NQ - 1);
        int pos = atomicAdd(&g_cellfill[b * NCELL + cell], 1);
        g_sorted[b * NQ + pos] = make_float4(p.x, p.y, p.z, __int_as_float(n));
    }
}

// ---------------------------------------------------------------------------
// K4: ball query via grid + per-warp bitmask, single-pass extraction.
// ---------------------------------------------------------------------------
__global__ __launch_bounds__(WARPS_B * 32)
void ball_query_grid_kernel(const float* __restrict__ new_xyz,
                            float* __restrict__ out) {
    __shared__ unsigned mask[WARPS_B][NQ / 32];     // 2 KB per warp
    __shared__ int      sh_idx[WARPS_B][NS];

    const int warp = threadIdx.x >> 5;
    const int lane = threadIdx.x & 31;
    const int center = blockIdx.x * WARPS_B + warp;
    const int b = center / SQ;
    const int s = center % SQ;

    const float cx = new_xyz[3 * center + 0];
    const float cy = new_xyz[3 * center + 1];
    const float cz = new_xyz[3 * center + 2];
    const float r2 = (float)(0.1 * 0.1);

    // zero bitmask with 128-bit stores: 4 rounds
    {
        uint4* m4 = (uint4*)mask[warp];
#pragma unroll
        for (int i = lane; i < NQ / 128; i += 32) m4[i] = make_uint4(0, 0, 0, 0);
    }
    __syncwarp();

    // neighbor cell ranges with guard band against boundary rounding
    const int x0 = max(0, (int)floorf((cx - 0.1f) * 10.0f - 0.002f));
    const int x1 = min(9, (int)floorf((cx + 0.1f) * 10.0f + 0.002f));
    const int y0 = max(0, (int)floorf((cy - 0.1f) * 10.0f - 0.002f));
    const int y1 = min(9, (int)floorf((cy + 0.1f) * 10.0f + 0.002f));
    const int z0 = max(0, (int)floorf((cz - 0.1f) * 10.0f - 0.002f));
    const int z1 = min(9, (int)floorf((cz + 0.1f) * 10.0f + 0.002f));

    const float4* __restrict__ srt = g_sorted + (size_t)b * NQ;
    const int* __restrict__ cs = g_cellstart + b * (NCELL + 1);

    for (int zc = z0; zc <= z1; zc++) {
        for (int yc = y0; yc <= y1; yc++) {
            int rowbase = (zc * 10 + yc) * 10;
            int st = cs[rowbase + x0];
            int en = cs[rowbase + x1 + 1];          // x-contiguous cells
            for (int ibase = st; ibase < en; ibase += 32) {
                int i = ibase + lane;
                if (i < en) {
                    float4 p = srt[i];
                    float dx = __fadd_rn(cx, -p.x);
                    float dy = __fadd_rn(cy, -p.y);
                    float dz = __fadd_rn(cz, -p.z);
                    float d2 = __fadd_rn(__fadd_rn(__fmul_rn(dx, dx), __fmul_rn(dy, dy)),
                                         __fmul_rn(dz, dz));
                    if (d2 < r2) {
                        int oi = __float_as_int(p.w);
                        atomicOr(&mask[warp][oi >> 5], 1u << (oi & 31));
                    }
                }
            }
        }
    }
    __syncwarp();

    // single-pass extraction: lane L owns indices [512L, 512L+512)
    const unsigned* mw = mask[warp] + lane * 16;
    int pc = 0;
#pragma unroll
    for (int j = 0; j < 16; j++) pc += __popc(mw[j]);
    int inc = pc;
#pragma unroll
    for (int d = 1; d < 32; d <<= 1) {
        int v = __shfl_up_sync(0xffffffffu, inc, d);
        if (lane >= d) inc += v;
    }
    const int cnt  = __shfl_sync(0xffffffffu, inc, 31);
    const int excl = inc - pc;
    if (pc > 0 && excl < NS) {
        int pos = excl;
        int base = lane * 512;
        for (int j = 0; j < 16 && pos < NS; j++) {
            unsigned w = mw[j];
            while (w) {
                int bpos = __ffs(w) - 1;
                w &= w - 1;
                sh_idx[warp][pos++] = base + j * 32 + bpos;
                if (pos >= NS) break;
            }
        }
    }
    __syncwarp();

    // lane k owns sample k; pad with first hit, 0 if none
    int myidx = (cnt == 0) ? 0 : sh_idx[warp][(lane < cnt) ? lane : 0];
    g_idx[center * NS + lane] = myidx;

    // grouped_xyz channels 0..2 (coalesced over lane=k)
    float4 p = g_xyzp[(size_t)b * NQ + myidx];
    const size_t chan_stride = (size_t)SQ * NS;
    float* ob = out + ((size_t)b * OUTC * SQ + s) * NS + lane;
    __stcs(ob + 0 * chan_stride, __fadd_rn(p.x, -cx));
    __stcs(ob + 1 * chan_stride, __fadd_rn(p.y, -cy));
    __stcs(ob + 2 * chan_stride, __fadd_rn(p.z, -cz));
}

// ---------------------------------------------------------------------------
// K5: feature grouping, one 128-thread block per center.
// ---------------------------------------------------------------------------
__global__ __launch_bounds__(128)
void group_feat_kernel(float* __restrict__ out) {
    __shared__ float4 sf4[NS][17];                  // pitch 17 float4 -> conflict-free
    __shared__ int    sidx[NS];

    const int center = blockIdx.x;
    const int b = center / SQ;
    const int s = center % SQ;
    const int tid = threadIdx.x;

    if (tid < NS) sidx[tid] = g_idx[center * NS + tid];
    __syncthreads();

    const float4* __restrict__ ft4 =
        (const float4*)(g_featT + (size_t)b * NQ * CQ);
    const int r  = tid >> 4;       // 0..7
    const int c4 = tid & 15;       // 0..15
#pragma unroll
    for (int r0 = 0; r0 < NS; r0 += 8)
        sf4[r0 + r][c4] = __ldg(ft4 + (size_t)sidx[r0 + r] * 16 + c4);
    __syncthreads();

    const int k = tid & 31;
    const int w = tid >> 5;        // 0..3
    const size_t chan_stride = (size_t)SQ * NS;
    float* ob = out + ((size_t)b * OUTC * SQ + s) * NS + k + 3 * chan_stride;
#pragma unroll
    for (int cc = w; cc < 16; cc += 4) {
        float4 v = sf4[k][cc];
        float* o = ob + (size_t)(4 * cc) * chan_stride;
        __stcs(o + 0 * chan_stride, v.x);
        __stcs(o + 1 * chan_stride, v.y);
        __stcs(o + 2 * chan_stride, v.z);
        __stcs(o + 3 * chan_stride, v.w);
    }
}

// ---------------------------------------------------------------------------
// Launch
// ---------------------------------------------------------------------------
extern "C" void kernel_launch(void* const* d_in, const int* in_sizes, int n_in,
                              void* d_out, int out_size) {
    const float* xyz     = (const float*)d_in[0];   // [B,N,3]
    const float* new_xyz = (const float*)d_in[1];   // [B,S,3]
    const float* feat    = (const float*)d_in[2];   // [B,C,N]
    float* out = (float*)d_out;                     // [B,67,S,NS]

    k1_hist<<<HB + NTILE, 256>>>(xyz, feat);        // hist + all transpose
    k2_scan<<<BQ, 256>>>();                         // per-batch cell scan
    k3_scatter<<<HB, 256>>>();                      // cell-order scatter

    ball_query_grid_kernel<<<(BQ * SQ) / WARPS_B, WARPS_B * 32>>>(new_xyz, out);

    group_feat_kernel<<<BQ * SQ, 128>>>(out);
}

// round 8
// speedup vs baseline: 1.0484x; 1.0484x over previous
#include <cuda_runtime.h>
#include <stdint.h>

// Fixed problem shapes
#define BQ 2
#define NQ 16384
#define SQ 4096
#define CQ 64
#define NS 32
#define OUTC 67
#define NCELL 1000            // 10x10x10 grid, cell = radius = 0.1
#define WARPS_B 8             // centers per ball-query block
#define HB 64                 // wide hist/scatter blocks
#define NTILE 2048            // transpose tiles (512 n x 2 c x 2 b)

// Device scratch (no allocations allowed). g_cellcnt starts zero (static
// init) and is re-zeroed by k2 each replay -> pipeline stateless under graphs.
__device__ float4 g_xyzp[BQ * NQ];                  // packed xyz, cell id in .w
__device__ float4 g_sorted[BQ * NQ];                // cell-sorted xyz, orig idx in .w
__device__ float  g_featT[(size_t)BQ * NQ * CQ];    // features [B,N,C]
__device__ int    g_idx[BQ * SQ * NS];              // final sample indices
__device__ int    g_cellcnt[BQ * NCELL];            // histogram
__device__ int    g_cellstart[BQ * (NCELL + 1)];    // exclusive prefix, [1000] = N
__device__ int    g_cellfill[BQ * NCELL];           // scatter cursors

__device__ __forceinline__ int cell_of(float v) {
    int c = (int)(v * 10.0f);
    return min(9, max(0, c));
}

// one 32x32 transpose tile of [B,C,N] -> [B,N,C]; id in [0, NTILE)
__device__ __forceinline__ void transpose_tile(const float* __restrict__ feat, int id) {
    __shared__ float tile[32][33];
    int n0 = (id & 511) * 32;
    int c0 = ((id >> 9) & 1) * 32;
    int b  = id >> 10;
    int tx = threadIdx.x & 31;
    int ty = threadIdx.x >> 5;                      // 0..7

#pragma unroll
    for (int j = 0; j < 32; j += 8)
        tile[ty + j][tx] = feat[((size_t)b * CQ + (c0 + ty + j)) * NQ + (n0 + tx)];
    __syncthreads();
#pragma unroll
    for (int j = 0; j < 32; j += 8)
        g_featT[((size_t)b * NQ + (n0 + ty + j)) * CQ + (c0 + tx)] = tile[tx][ty + j];
}

// ---------------------------------------------------------------------------
// K1: blocks 0..HB-1 = pack + global-atomic histogram; rest = ALL transpose
// ---------------------------------------------------------------------------
__global__ __launch_bounds__(256)
void k1_hist(const float* __restrict__ xyz, const float* __restrict__ feat) {
    if (blockIdx.x < HB) {
        int i = blockIdx.x * (BQ * NQ / HB) + threadIdx.x;   // 512 pts per block
        int end = (blockIdx.x + 1) * (BQ * NQ / HB);
        for (; i < end; i += 256) {
            float x = xyz[3 * i + 0], y = xyz[3 * i + 1], z = xyz[3 * i + 2];
            int cell = (cell_of(z) * 10 + cell_of(y)) * 10 + cell_of(x);
            g_xyzp[i] = make_float4(x, y, z, __int_as_float(cell));
            int b = i >> 14;
            atomicAdd(&g_cellcnt[b * NCELL + cell], 1);
        }
    } else {
        transpose_tile(feat, blockIdx.x - HB);               // all 2048 tiles
    }
}

// ---------------------------------------------------------------------------
// K2: per-batch scan over 1000 cells (hierarchical, 3 barriers);
//     re-zeroes counts, fills cellstart + cursors.
// ---------------------------------------------------------------------------
__global__ __launch_bounds__(256)
void k2_scan() {
    __shared__ int wsum[8];
    __shared__ int wbase[8];
    const int b = blockIdx.x;
    const int t = threadIdx.x;
    const int lane = t & 31, wid = t >> 5;

    int cnt4[4];
    int own = 0;
    if (t < 250) {
#pragma unroll
        for (int j = 0; j < 4; j++) {
            cnt4[j] = g_cellcnt[b * NCELL + 4 * t + j];
            own += cnt4[j];
        }
    }
    int inc = own;
#pragma unroll
    for (int d = 1; d < 32; d <<= 1) {
        int v = __shfl_up_sync(0xffffffffu, inc, d);
        if (lane >= d) inc += v;
    }
    if (lane == 31) wsum[wid] = inc;
    __syncthreads();
    if (t == 0) {
        int run = 0;
#pragma unroll
        for (int w = 0; w < 8; w++) { wbase[w] = run; run += wsum[w]; }
    }
    __syncthreads();

    if (t < 250) {
        int run = wbase[wid] + inc - own;            // exclusive base
#pragma unroll
        for (int j = 0; j < 4; j++) {
            int bin = 4 * t + j;
            g_cellstart[b * (NCELL + 1) + bin] = run;
            g_cellfill[b * NCELL + bin] = run;
            g_cellcnt[b * NCELL + bin] = 0;          // stateless for replay
            run += cnt4[j];
        }
    }
    if (t == 0) g_cellstart[b * (NCELL + 1) + NCELL] = NQ;
}

// ---------------------------------------------------------------------------
// K3: scatter into cell order (cell id cached in g_xyzp.w)
// ---------------------------------------------------------------------------
__global__ __launch_bounds__(256)
void k3_scatter() {
    int i = blockIdx.x * (BQ * NQ / HB) + threadIdx.x;
    int end = (blockIdx.x + 1) * (BQ * NQ / HB);
    for (; i < end; i += 256) {
        float4 p = g_xyzp[i];
        int cell = __float_as_int(p.w);
        int b = i >> 14, n = i & (NQ - 1);
        int pos = atomicAdd(&g_cellfill[b * NCELL + cell], 1);
        g_sorted[b * NQ + pos] = make_float4(p.x, p.y, p.z, __int_as_float(n));
    }
}

// ---------------------------------------------------------------------------
// K4: ball query. Bitmask stored TRANSPOSED: global word w lives at smem
// offset (w&15)*32 + (w>>4), so lane L owns global words 16L..16L+15 but
// reads them at stride 32 (bank = L) -> conflict-free extraction while
// preserving ascending-original-index order.
// ---------------------------------------------------------------------------
__global__ __launch_bounds__(WARPS_B * 32)
void ball_query_grid_kernel(const float* __restrict__ new_xyz,
                            float* __restrict__ out) {
    __shared__ unsigned mask[WARPS_B][NQ / 32];     // 2 KB per warp
    __shared__ int      sh_idx[WARPS_B][NS];

    const int warp = threadIdx.x >> 5;
    const int lane = threadIdx.x & 31;
    const int center = blockIdx.x * WARPS_B + warp;
    const int b = center / SQ;
    const int s = center % SQ;

    const float cx = new_xyz[3 * center + 0];
    const float cy = new_xyz[3 * center + 1];
    const float cz = new_xyz[3 * center + 2];
    const float r2 = (float)(0.1 * 0.1);

    // zero bitmask with 128-bit stores: 4 rounds
    {
        uint4* m4 = (uint4*)mask[warp];
#pragma unroll
        for (int i = lane; i < NQ / 128; i += 32) m4[i] = make_uint4(0, 0, 0, 0);
    }
    __syncwarp();

    // neighbor cell ranges with guard band against boundary rounding
    const int x0 = max(0, (int)floorf((cx - 0.1f) * 10.0f - 0.002f));
    const int x1 = min(9, (int)floorf((cx + 0.1f) * 10.0f + 0.002f));
    const int y0 = max(0, (int)floorf((cy - 0.1f) * 10.0f - 0.002f));
    const int y1 = min(9, (int)floorf((cy + 0.1f) * 10.0f + 0.002f));
    const int z0 = max(0, (int)floorf((cz - 0.1f) * 10.0f - 0.002f));
    const int z1 = min(9, (int)floorf((cz + 0.1f) * 10.0f + 0.002f));

    const float4* __restrict__ srt = g_sorted + (size_t)b * NQ;
    const int* __restrict__ cs = g_cellstart + b * (NCELL + 1);

    for (int zc = z0; zc <= z1; zc++) {
        for (int yc = y0; yc <= y1; yc++) {
            int rowbase = (zc * 10 + yc) * 10;
            int st = cs[rowbase + x0];
            int en = cs[rowbase + x1 + 1];          // x-contiguous cells
            for (int ibase = st; ibase < en; ibase += 32) {
                int i = ibase + lane;
                if (i < en) {
                    float4 p = srt[i];
                    float dx = __fadd_rn(cx, -p.x);
                    float dy = __fadd_rn(cy, -p.y);
                    float dz = __fadd_rn(cz, -p.z);
                    float d2 = __fadd_rn(__fadd_rn(__fmul_rn(dx, dx), __fmul_rn(dy, dy)),
                                         __fmul_rn(dz, dz));
                    if (d2 < r2) {
                        int oi = __float_as_int(p.w);
                        int w  = oi >> 5;
                        // transposed slot: (w&15)*32 + (w>>4)
                        atomicOr(&mask[warp][((w & 15) << 5) + (w >> 4)],
                                 1u << (oi & 31));
                    }
                }
            }
        }
    }
    __syncwarp();

    // single-pass extraction, conflict-free: round j reads smem[j*32 + lane]
    const unsigned* mw = mask[warp];
    unsigned wreg[16];
    int pc = 0;
#pragma unroll
    for (int j = 0; j < 16; j++) {
        wreg[j] = mw[(j << 5) + lane];              // global word 16*lane + j
        pc += __popc(wreg[j]);
    }
    int inc = pc;
#pragma unroll
    for (int d = 1; d < 32; d <<= 1) {
        int v = __shfl_up_sync(0xffffffffu, inc, d);
        if (lane >= d) inc += v;
    }
    const int cnt  = __shfl_sync(0xffffffffu, inc, 31);
    const int excl = inc - pc;
    if (pc > 0 && excl < NS) {
        int pos = excl;
        int base = lane * 512;
#pragma unroll
        for (int j = 0; j < 16; j++) {
            unsigned w = wreg[j];
            while (w && pos < NS) {
                int bpos = __ffs(w) - 1;
                w &= w - 1;
                sh_idx[warp][pos++] = base + (j << 5) + bpos;
            }
        }
    }
    __syncwarp();

    // lane k owns sample k; pad with first hit, 0 if none
    int myidx = (cnt == 0) ? 0 : sh_idx[warp][(lane < cnt) ? lane : 0];
    g_idx[center * NS + lane] = myidx;

    // grouped_xyz channels 0..2 (coalesced over lane=k)
    float4 p = g_xyzp[(size_t)b * NQ + myidx];
    const size_t chan_stride = (size_t)SQ * NS;
    float* ob = out + ((size_t)b * OUTC * SQ + s) * NS + lane;
    __stcs(ob + 0 * chan_stride, __fadd_rn(p.x, -cx));
    __stcs(ob + 1 * chan_stride, __fadd_rn(p.y, -cy));
    __stcs(ob + 2 * chan_stride, __fadd_rn(p.z, -cz));
}

// ---------------------------------------------------------------------------
// K5: feature grouping, one 128-thread block per center.
// ---------------------------------------------------------------------------
__global__ __launch_bounds__(128)
void group_feat_kernel(float* __restrict__ out) {
    __shared__ float4 sf4[NS][17];                  // pitch 17 float4 -> conflict-free
    __shared__ int    sidx[NS];

    const int center = blockIdx.x;
    const int b = center / SQ;
    const int s = center % SQ;
    const int tid = threadIdx.x;

    if (tid < NS) sidx[tid] = g_idx[center * NS + tid];
    __syncthreads();

    const float4* __restrict__ ft4 =
        (const float4*)(g_featT + (size_t)b * NQ * CQ);
    const int r  = tid >> 4;       // 0..7
    const int c4 = tid & 15;       // 0..15
#pragma unroll
    for (int r0 = 0; r0 < NS; r0 += 8)
        sf4[r0 + r][c4] = __ldg(ft4 + (size_t)sidx[r0 + r] * 16 + c4);
    __syncthreads();

    const int k = tid & 31;
    const int w = tid >> 5;        // 0..3
    const size_t chan_stride = (size_t)SQ * NS;
    float* ob = out + ((size_t)b * OUTC * SQ + s) * NS + k + 3 * chan_stride;
#pragma unroll
    for (int cc = w; cc < 16; cc += 4) {
        float4 v = sf4[k][cc];
        float* o = ob + (size_t)(4 * cc) * chan_stride;
        __stcs(o + 0 * chan_stride, v.x);
        __stcs(o + 1 * chan_stride, v.y);
        __stcs(o + 2 * chan_stride, v.z);
        __stcs(o + 3 * chan_stride, v.w);
    }
}

// ---------------------------------------------------------------------------
// Launch
// ---------------------------------------------------------------------------
extern "C" void kernel_launch(void* const* d_in, const int* in_sizes, int n_in,
                              void* d_out, int out_size) {
    const float* xyz     = (const float*)d_in[0];   // [B,N,3]
    const float* new_xyz = (const float*)d_in[1];   // [B,S,3]
    const float* feat    = (const float*)d_in[2];   // [B,C,N]
    float* out = (float*)d_out;                     // [B,67,S,NS]

    k1_hist<<<HB + NTILE, 256>>>(xyz, feat);        // hist + all transpose
    k2_scan<<<BQ, 256>>>();                         // per-batch cell scan
    k3_scatter<<<HB, 256>>>();                      // cell-order scatter

    ball_query_grid_kernel<<<(BQ * SQ) / WARPS_B, WARPS_B * 32>>>(new_xyz, out);

    group_feat_kernel<<<BQ * SQ, 128>>>(out);
}